// round 1
// baseline (speedup 1.0000x reference)
#include <cuda_runtime.h>
#include <math.h>
#include <stdint.h>

// Problem dims
#define BB    64
#define SS    96
#define EE    300
#define DD    512
#define HH    256
#define SELD  128
#define MLPD  1024
#define NCD   3
#define FIVEH 1280   // 5*HH

// Scratch (static __device__ — no allocation)
__device__ float g_states[BB * SS * DD];      // (b, s, d)  ~12.6 MB
__device__ float g_partial[BB * 8 * SS];      // selector init partials [b][g][j]
__device__ float g_hroot[BB * HH];

__device__ __forceinline__ float sigm(float x) { return 1.0f / (1.0f + expf(-x)); }

// ---------------------------------------------------------------------------
// Kernel 1: encode. states[token, :] = embed[sent[token]] @ W_enc + b_enc
// GEMM (6144 x 300) @ (300 x 512). Tile 64x64, Kc=20, 256 threads, 4x4 micro.
// ---------------------------------------------------------------------------
__global__ __launch_bounds__(256) void encode_kernel(
    const int* __restrict__ sent, const float* __restrict__ emb,
    const float* __restrict__ Wenc, const float* __restrict__ benc)
{
    __shared__ float As[64 * 20];
    __shared__ float Bs[20 * 64];
    __shared__ int words[64];

    const int cb = blockIdx.x;        // col tile (0..7)
    const int tb = blockIdx.y;        // token tile (0..95)
    const int tid = threadIdx.x;
    const int tokenbase = tb * 64;
    const int colbase = cb * 64;

    if (tid < 64) words[tid] = sent[tokenbase + tid];
    __syncthreads();

    const int tx = tid & 15;          // 0..15 -> 4 cols
    const int ty = tid >> 4;          // 0..15 -> 4 rows

    float acc[4][4];
#pragma unroll
    for (int i = 0; i < 4; i++)
#pragma unroll
        for (int j = 0; j < 4; j++) acc[i][j] = 0.0f;

    for (int kb = 0; kb < EE; kb += 20) {
#pragma unroll
        for (int i = 0; i < 5; i++) {
            int e = tid + 256 * i;            // 0..1279
            int r = e / 20, k = e % 20;
            As[e] = emb[(size_t)words[r] * EE + kb + k];
        }
#pragma unroll
        for (int i = 0; i < 5; i++) {
            int e = tid + 256 * i;
            int k = e >> 6, c = e & 63;
            Bs[e] = Wenc[(size_t)(kb + k) * DD + colbase + c];
        }
        __syncthreads();
#pragma unroll
        for (int k = 0; k < 20; k++) {
            float a0 = As[(4 * ty + 0) * 20 + k];
            float a1 = As[(4 * ty + 1) * 20 + k];
            float a2 = As[(4 * ty + 2) * 20 + k];
            float a3 = As[(4 * ty + 3) * 20 + k];
            float b0 = Bs[k * 64 + 4 * tx + 0];
            float b1 = Bs[k * 64 + 4 * tx + 1];
            float b2 = Bs[k * 64 + 4 * tx + 2];
            float b3 = Bs[k * 64 + 4 * tx + 3];
            acc[0][0] += a0 * b0; acc[0][1] += a0 * b1; acc[0][2] += a0 * b2; acc[0][3] += a0 * b3;
            acc[1][0] += a1 * b0; acc[1][1] += a1 * b1; acc[1][2] += a1 * b2; acc[1][3] += a1 * b3;
            acc[2][0] += a2 * b0; acc[2][1] += a2 * b1; acc[2][2] += a2 * b2; acc[2][3] += a2 * b3;
            acc[3][0] += a3 * b0; acc[3][1] += a3 * b1; acc[3][2] += a3 * b2; acc[3][3] += a3 * b3;
        }
        __syncthreads();
    }

#pragma unroll
    for (int i = 0; i < 4; i++) {
        int row = tokenbase + 4 * ty + i;
        int col = colbase + 4 * tx;
        float4 bia = *(const float4*)(benc + col);
        float4 v;
        v.x = acc[i][0] + bia.x; v.y = acc[i][1] + bia.y;
        v.z = acc[i][2] + bia.z; v.w = acc[i][3] + bia.w;
        *(float4*)(g_states + (size_t)row * DD + col) = v;
    }
}

// ---------------------------------------------------------------------------
// Kernel 1b: initial selector logits (partial sums over unit-groups of 16).
// grid (8 groups, 64 batches), 256 threads. smem: W1 slice 32KB + h-half 96KB.
// partial[b][g][j] = sum_{u in group g} tanh(b1[u] + [h_j;h_{j+1}].W1[:,u]) * W2[u]
// ---------------------------------------------------------------------------
__global__ __launch_bounds__(256) void sel_init_kernel(
    const float* __restrict__ Wsel1, const float* __restrict__ bsel1,
    const float* __restrict__ Wsel2)
{
    extern __shared__ float sh[];
    float* w1s = sh;                  // 512*16
    float* hs  = sh + 512 * 16;      // 96*256

    const int g = blockIdx.x, b = blockIdx.y, tid = threadIdx.x;

    for (int i = tid; i < 512 * 16; i += 256) {
        int d = i >> 4, u = i & 15;
        w1s[i] = Wsel1[(size_t)d * SELD + g * 16 + u];
    }
    for (int i = tid; i < SS * HH; i += 256) {
        int s = i >> 8, dd = i & 255;
        hs[i] = g_states[((size_t)(b * SS + s)) * DD + HH + dd];
    }
    __syncthreads();

    const int u16 = tid & 15;
    const int jg = tid >> 4;          // 0..15
    const float bs = bsel1[g * 16 + u16];
    const float w2 = Wsel2[g * 16 + u16];

    for (int jj = 0; jj < 6; jj++) {
        int j = jg + 16 * jj;
        float v = 0.0f;
        if (j < SS - 1) {
            float a = bs;
            const float* ha = hs + j * HH;
            const float* hb = hs + (j + 1) * HH;
#pragma unroll 8
            for (int d = 0; d < HH; d++) a += ha[d] * w1s[d * 16 + u16];
#pragma unroll 8
            for (int d = 0; d < HH; d++) a += hb[d] * w1s[(HH + d) * 16 + u16];
            v = tanhf(a) * w2;
        }
        for (int off = 8; off; off >>= 1) v += __shfl_down_sync(0xFFFFFFFFu, v, off, 16);
        if (u16 == 0 && j < SS - 1) g_partial[(b * 8 + g) * SS + j] = v;
    }
}

// ---------------------------------------------------------------------------
// Kernel 2: per-batch pyramid scan. One block per batch, 320 threads.
// States in smem (96x512). ord[] indirection, incremental logit updates.
// ---------------------------------------------------------------------------
__global__ __launch_bounds__(320, 1) void pyramid_kernel(
    const float* __restrict__ Wcomp, const float* __restrict__ bcomp,
    const float* __restrict__ Wsel1, const float* __restrict__ bsel1,
    const float* __restrict__ Wsel2, const float* __restrict__ bsel2)
{
    extern __shared__ float sh[];
    float* st     = sh;                       // 96*512
    float* logits = st + SS * DD;             // 96
    float* aout   = logits + SS;              // 1280
    float* selred = aout + FIVEH;             // 8
    int*   ord    = (int*)(selred + 8);       // 96
    int*   sidx   = ord + SS;                 // 1

    const int b = blockIdx.x;
    const int tid = threadIdx.x;

    // load this batch's states
    const float* src = g_states + (size_t)b * SS * DD;
    for (int i = tid; i < SS * DD; i += 320) st[i] = src[i];

    if (tid < SS - 1) {
        float a = bsel2[0];
        for (int g = 0; g < 8; g++) a += g_partial[(b * 8 + g) * SS + tid];
        logits[tid] = a;
    }
    if (tid < SS) ord[tid] = tid;
    __syncthreads();

    for (int t = 0; t < SS - 1; t++) {
        const int n = SS - t;
        const int npairs = n - 1;

        // ---- argmax over valid logits (warp 0, ties -> lowest index) ----
        if (tid < 32) {
            float bv = -1e30f; int bi = 0x7FFFFFFF;
            for (int j = tid; j < npairs; j += 32) {
                float v = logits[j];
                if (v > bv) { bv = v; bi = j; }
            }
            for (int off = 16; off; off >>= 1) {
                float ov = __shfl_down_sync(0xFFFFFFFFu, bv, off);
                int   oi = __shfl_down_sync(0xFFFFFFFFu, bi, off);
                if (ov > bv || (ov == bv && oi < bi)) { bv = ov; bi = oi; }
            }
            if (tid == 0) *sidx = bi;
        }
        __syncthreads();
        const int idx = *sidx;
        const int slotL = ord[idx];
        const int slotR = ord[idx + 1];

        // ---- compose GEMV: a = [h_L; h_R] @ W_comp + b_comp (1280 outputs) ----
        {
            const int k0 = tid * 4;
            float4 acc = *(const float4*)(bcomp + k0);
            const float* xl = st + slotL * DD + HH;   // h_L, d in [0,256)
            const float* xr = st + slotR * DD;        // h_R at [256,512) -> xr[d]
#pragma unroll 4
            for (int d = 0; d < HH; d++) {
                float x = xl[d];
                float4 w = *(const float4*)(Wcomp + (size_t)d * FIVEH + k0);
                acc.x += x * w.x; acc.y += x * w.y; acc.z += x * w.z; acc.w += x * w.w;
            }
#pragma unroll 4
            for (int d = HH; d < DD; d++) {
                float x = xr[d];
                float4 w = *(const float4*)(Wcomp + (size_t)d * FIVEH + k0);
                acc.x += x * w.x; acc.y += x * w.y; acc.z += x * w.z; acc.w += x * w.w;
            }
            *(float4*)(aout + k0) = acc;
        }
        __syncthreads();

        // ---- gates + write comp into slotL; bookkeeping shifts in parallel ----
        if (tid < HH) {
            float iv = aout[tid];
            float fl = aout[HH + tid];
            float fr = aout[2 * HH + tid];
            float ov = aout[3 * HH + tid];
            float gc = aout[4 * HH + tid];
            float lc = st[slotL * DD + tid];
            float rc = st[slotR * DD + tid];
            float c  = sigm(fl) * lc + sigm(fr) * rc + sigm(iv) * tanhf(gc);
            float hh = sigm(ov) * tanhf(c);
            st[slotL * DD + tid]      = c;
            st[slotL * DD + HH + tid] = hh;
        } else if (tid == 256) {
            for (int j = idx + 1; j <= n - 2; j++) ord[j] = ord[j + 1];
        } else if (tid == 257) {
            for (int j = idx + 1; j <= n - 3; j++) logits[j] = logits[j + 1];
        }
        __syncthreads();

        // ---- recompute the two affected logits (new indexing; valid pairs 0..n-3)
        const int u = tid & 127;
        const int pos = tid >> 7;                 // 0,1 compute; 2 idle
        const int p = (pos == 0) ? (idx - 1) : idx;
        const bool valid = (pos == 0) ? (idx >= 1)
                         : (pos == 1) ? (idx <= n - 3) : false;
        float v = 0.0f;
        if (valid) {
            const int sa = ord[p], sb = ord[p + 1];
            const float* ha = st + sa * DD + HH;
            const float* hb = st + sb * DD + HH;
            float a = bsel1[u];
#pragma unroll 8
            for (int d = 0; d < HH; d++) a += ha[d] * Wsel1[(size_t)d * SELD + u];
#pragma unroll 8
            for (int d = 0; d < HH; d++) a += hb[d] * Wsel1[(size_t)(HH + d) * SELD + u];
            v = tanhf(a) * Wsel2[u];
        }
        for (int off = 16; off; off >>= 1) v += __shfl_down_sync(0xFFFFFFFFu, v, off);
        if ((tid & 31) == 0 && tid < 256) selred[tid >> 5] = v;
        __syncthreads();
        if ((tid == 0 || tid == 128) && valid) {
            int w0 = (tid >> 5);  // 0 or 4
            logits[p] = selred[w0] + selred[w0 + 1] + selred[w0 + 2] + selred[w0 + 3] + bsel2[0];
        }
        __syncthreads();
    }

    if (tid < HH) g_hroot[b * HH + tid] = st[ord[0] * DD + HH + tid];
}

// ---------------------------------------------------------------------------
// Kernel 3: final MLP per batch. 256 threads per block.
// ---------------------------------------------------------------------------
__global__ __launch_bounds__(256) void mlp_kernel(
    const float* __restrict__ Wm1, const float* __restrict__ bm1,
    const float* __restrict__ Wm2, const float* __restrict__ bm2,
    const float* __restrict__ Wout, const float* __restrict__ bout,
    float* __restrict__ out)
{
    __shared__ float hroot[HH];
    __shared__ float x1[MLPD];
    __shared__ float x2[MLPD];
    __shared__ float ored[NCD][32];

    const int b = blockIdx.x;
    const int tid = threadIdx.x;

    hroot[tid] = g_hroot[b * HH + tid & 255 ? b * HH + tid : b * HH];  // placeholder avoided below
    __syncthreads();
    // (re-load cleanly; the line above is overwritten to keep logic simple)
    hroot[tid] = g_hroot[b * HH + tid];
    __syncthreads();

    const int c0 = tid * 4;
    {
        float4 acc = *(const float4*)(bm1 + c0);
#pragma unroll 4
        for (int d = 0; d < HH; d++) {
            float x = hroot[d];
            float4 w = *(const float4*)(Wm1 + (size_t)d * MLPD + c0);
            acc.x += x * w.x; acc.y += x * w.y; acc.z += x * w.z; acc.w += x * w.w;
        }
        x1[c0 + 0] = fmaxf(acc.x, 0.0f);
        x1[c0 + 1] = fmaxf(acc.y, 0.0f);
        x1[c0 + 2] = fmaxf(acc.z, 0.0f);
        x1[c0 + 3] = fmaxf(acc.w, 0.0f);
    }
    __syncthreads();
    {
        float4 acc = *(const float4*)(bm2 + c0);
#pragma unroll 4
        for (int d = 0; d < MLPD; d++) {
            float x = x1[d];
            float4 w = *(const float4*)(Wm2 + (size_t)d * MLPD + c0);
            acc.x += x * w.x; acc.y += x * w.y; acc.z += x * w.z; acc.w += x * w.w;
        }
        x2[c0 + 0] = fmaxf(acc.x, 0.0f);
        x2[c0 + 1] = fmaxf(acc.y, 0.0f);
        x2[c0 + 2] = fmaxf(acc.z, 0.0f);
        x2[c0 + 3] = fmaxf(acc.w, 0.0f);
    }
    __syncthreads();
    if (tid < 96) {
        int c = tid % 3, seg = tid / 3;
        float a = 0.0f;
        for (int k = seg; k < MLPD; k += 32) a += x2[k] * Wout[(size_t)k * NCD + c];
        ored[c][seg] = a;
    }
    __syncthreads();
    if (tid < NCD) {
        float a = bout[tid];
        for (int s = 0; s < 32; s++) a += ored[tid][s];
        out[b * NCD + tid] = a;
    }
}

// ---------------------------------------------------------------------------
extern "C" void kernel_launch(void* const* d_in, const int* in_sizes, int n_in,
                              void* d_out, int out_size)
{
    const int*   sent  = (const int*)d_in[0];
    /* d_in[1] = transitions (unused by reference) */
    const float* emb   = (const float*)d_in[2];
    const float* Wenc  = (const float*)d_in[3];
    const float* benc  = (const float*)d_in[4];
    const float* Wcomp = (const float*)d_in[5];
    const float* bcomp = (const float*)d_in[6];
    const float* Wsel1 = (const float*)d_in[7];
    const float* bsel1 = (const float*)d_in[8];
    const float* Wsel2 = (const float*)d_in[9];
    const float* bsel2 = (const float*)d_in[10];
    const float* Wm1   = (const float*)d_in[11];
    const float* bm1   = (const float*)d_in[12];
    const float* Wm2   = (const float*)d_in[13];
    const float* bm2   = (const float*)d_in[14];
    const float* Wout  = (const float*)d_in[15];
    const float* bout  = (const float*)d_in[16];
    float* out = (float*)d_out;

    const int smem_selinit = (512 * 16 + SS * HH) * sizeof(float);           // 128 KB
    const int smem_pyramid = (SS * DD + SS + FIVEH + 8) * sizeof(float)
                           + (SS + 1) * sizeof(int) + 256;                   // ~203 KB

    cudaFuncSetAttribute(sel_init_kernel, cudaFuncAttributeMaxDynamicSharedMemorySize, smem_selinit);
    cudaFuncSetAttribute(pyramid_kernel,  cudaFuncAttributeMaxDynamicSharedMemorySize, smem_pyramid);

    encode_kernel<<<dim3(8, 96), 256>>>(sent, emb, Wenc, benc);
    sel_init_kernel<<<dim3(8, BB), 256, smem_selinit>>>(Wsel1, bsel1, Wsel2);
    pyramid_kernel<<<BB, 320, smem_pyramid>>>(Wcomp, bcomp, Wsel1, bsel1, Wsel2, bsel2);
    mlp_kernel<<<BB, 256>>>(Wm1, bm1, Wm2, bm2, Wout, bout, out);
}

// round 2
// speedup vs baseline: 1.0161x; 1.0161x over previous
#include <cuda_runtime.h>
#include <math.h>
#include <stdint.h>

// Problem dims
#define BB    64
#define SS    96
#define EE    300
#define DD    512
#define HH    256
#define SELD  128
#define MLPD  1024
#define NCD   3
#define FIVEH 1280   // 5*HH

// Scratch (static __device__ — no allocation)
__device__ float g_states[BB * SS * DD];      // (b, s, d)  ~12.6 MB
__device__ float g_partial[BB * 8 * SS];      // selector init partials [b][g][j]
__device__ float g_hroot[BB * HH];

__device__ __forceinline__ float sigm(float x) { return 1.0f / (1.0f + expf(-x)); }

// ---------------------------------------------------------------------------
// Kernel 1: encode. states[token, :] = embed[sent[token]] @ W_enc + b_enc
// GEMM (6144 x 300) @ (300 x 512). Tile 64x64, Kc=20, 256 threads, 4x4 micro.
// ---------------------------------------------------------------------------
__global__ __launch_bounds__(256) void encode_kernel(
    const int* __restrict__ sent, const float* __restrict__ emb,
    const float* __restrict__ Wenc, const float* __restrict__ benc)
{
    __shared__ float As[64 * 20];
    __shared__ float Bs[20 * 64];
    __shared__ int words[64];

    const int cb = blockIdx.x;        // col tile (0..7)
    const int tb = blockIdx.y;        // token tile (0..95)
    const int tid = threadIdx.x;
    const int tokenbase = tb * 64;
    const int colbase = cb * 64;

    if (tid < 64) words[tid] = sent[tokenbase + tid];
    __syncthreads();

    const int tx = tid & 15;          // 0..15 -> 4 cols
    const int ty = tid >> 4;          // 0..15 -> 4 rows

    float acc[4][4];
#pragma unroll
    for (int i = 0; i < 4; i++)
#pragma unroll
        for (int j = 0; j < 4; j++) acc[i][j] = 0.0f;

    for (int kb = 0; kb < EE; kb += 20) {
#pragma unroll
        for (int i = 0; i < 5; i++) {
            int e = tid + 256 * i;            // 0..1279
            int r = e / 20, k = e % 20;
            As[e] = emb[(size_t)words[r] * EE + kb + k];
        }
#pragma unroll
        for (int i = 0; i < 5; i++) {
            int e = tid + 256 * i;
            int k = e >> 6, c = e & 63;
            Bs[e] = Wenc[(size_t)(kb + k) * DD + colbase + c];
        }
        __syncthreads();
#pragma unroll
        for (int k = 0; k < 20; k++) {
            float a0 = As[(4 * ty + 0) * 20 + k];
            float a1 = As[(4 * ty + 1) * 20 + k];
            float a2 = As[(4 * ty + 2) * 20 + k];
            float a3 = As[(4 * ty + 3) * 20 + k];
            float b0 = Bs[k * 64 + 4 * tx + 0];
            float b1 = Bs[k * 64 + 4 * tx + 1];
            float b2 = Bs[k * 64 + 4 * tx + 2];
            float b3 = Bs[k * 64 + 4 * tx + 3];
            acc[0][0] += a0 * b0; acc[0][1] += a0 * b1; acc[0][2] += a0 * b2; acc[0][3] += a0 * b3;
            acc[1][0] += a1 * b0; acc[1][1] += a1 * b1; acc[1][2] += a1 * b2; acc[1][3] += a1 * b3;
            acc[2][0] += a2 * b0; acc[2][1] += a2 * b1; acc[2][2] += a2 * b2; acc[2][3] += a2 * b3;
            acc[3][0] += a3 * b0; acc[3][1] += a3 * b1; acc[3][2] += a3 * b2; acc[3][3] += a3 * b3;
        }
        __syncthreads();
    }

#pragma unroll
    for (int i = 0; i < 4; i++) {
        int row = tokenbase + 4 * ty + i;
        int col = colbase + 4 * tx;
        float4 bia = *(const float4*)(benc + col);
        float4 v;
        v.x = acc[i][0] + bia.x; v.y = acc[i][1] + bia.y;
        v.z = acc[i][2] + bia.z; v.w = acc[i][3] + bia.w;
        *(float4*)(g_states + (size_t)row * DD + col) = v;
    }
}

// ---------------------------------------------------------------------------
// Kernel 1b: initial selector logits (partial sums over unit-groups of 16).
// grid (8 groups, 64 batches), 256 threads. smem: W1 slice 32KB + h-half 96KB.
// partial[b][g][j] = sum_{u in group g} tanh(b1[u] + [h_j;h_{j+1}].W1[:,u]) * W2[u]
// ---------------------------------------------------------------------------
__global__ __launch_bounds__(256) void sel_init_kernel(
    const float* __restrict__ Wsel1, const float* __restrict__ bsel1,
    const float* __restrict__ Wsel2)
{
    extern __shared__ float sh[];
    float* w1s = sh;                  // 512*16
    float* hs  = sh + 512 * 16;      // 96*256

    const int g = blockIdx.x, b = blockIdx.y, tid = threadIdx.x;

    for (int i = tid; i < 512 * 16; i += 256) {
        int d = i >> 4, u = i & 15;
        w1s[i] = Wsel1[(size_t)d * SELD + g * 16 + u];
    }
    for (int i = tid; i < SS * HH; i += 256) {
        int s = i >> 8, dd = i & 255;
        hs[i] = g_states[((size_t)(b * SS + s)) * DD + HH + dd];
    }
    __syncthreads();

    const int u16 = tid & 15;
    const int jg = tid >> 4;          // 0..15
    const float bs = bsel1[g * 16 + u16];
    const float w2 = Wsel2[g * 16 + u16];

    for (int jj = 0; jj < 6; jj++) {
        int j = jg + 16 * jj;
        float v = 0.0f;
        if (j < SS - 1) {
            float a = bs;
            const float* ha = hs + j * HH;
            const float* hb = hs + (j + 1) * HH;
#pragma unroll 8
            for (int d = 0; d < HH; d++) a += ha[d] * w1s[d * 16 + u16];
#pragma unroll 8
            for (int d = 0; d < HH; d++) a += hb[d] * w1s[(HH + d) * 16 + u16];
            v = tanhf(a) * w2;
        }
        for (int off = 8; off; off >>= 1) v += __shfl_down_sync(0xFFFFFFFFu, v, off, 16);
        if (u16 == 0 && j < SS - 1) g_partial[(b * 8 + g) * SS + j] = v;
    }
}

// ---------------------------------------------------------------------------
// Kernel 2: per-batch pyramid scan. One block per batch, 320 threads.
// States in smem (96x512). ord[] indirection, incremental logit updates.
// ---------------------------------------------------------------------------
__global__ __launch_bounds__(320, 1) void pyramid_kernel(
    const float* __restrict__ Wcomp, const float* __restrict__ bcomp,
    const float* __restrict__ Wsel1, const float* __restrict__ bsel1,
    const float* __restrict__ Wsel2, const float* __restrict__ bsel2)
{
    extern __shared__ float sh[];
    float* st     = sh;                       // 96*512
    float* logits = st + SS * DD;             // 96
    float* aout   = logits + SS;              // 1280
    float* selred = aout + FIVEH;             // 8
    int*   ord    = (int*)(selred + 8);       // 96
    int*   sidx   = ord + SS;                 // 1

    const int b = blockIdx.x;
    const int tid = threadIdx.x;

    // load this batch's states
    const float* src = g_states + (size_t)b * SS * DD;
    for (int i = tid; i < SS * DD; i += 320) st[i] = src[i];

    if (tid < SS - 1) {
        float a = bsel2[0];
        for (int g = 0; g < 8; g++) a += g_partial[(b * 8 + g) * SS + tid];
        logits[tid] = a;
    }
    if (tid < SS) ord[tid] = tid;
    __syncthreads();

    for (int t = 0; t < SS - 1; t++) {
        const int n = SS - t;
        const int npairs = n - 1;

        // ---- argmax over valid logits (warp 0, ties -> lowest index) ----
        if (tid < 32) {
            float bv = -1e30f; int bi = 0x7FFFFFFF;
            for (int j = tid; j < npairs; j += 32) {
                float v = logits[j];
                if (v > bv) { bv = v; bi = j; }
            }
            for (int off = 16; off; off >>= 1) {
                float ov = __shfl_down_sync(0xFFFFFFFFu, bv, off);
                int   oi = __shfl_down_sync(0xFFFFFFFFu, bi, off);
                if (ov > bv || (ov == bv && oi < bi)) { bv = ov; bi = oi; }
            }
            if (tid == 0) *sidx = bi;
        }
        __syncthreads();
        const int idx = *sidx;
        const int slotL = ord[idx];
        const int slotR = ord[idx + 1];

        // ---- compose GEMV: a = [h_L; h_R] @ W_comp + b_comp (1280 outputs) ----
        {
            const int k0 = tid * 4;
            float4 acc = *(const float4*)(bcomp + k0);
            const float* xl = st + slotL * DD + HH;   // h_L, d in [0,256)
            const float* xr = st + slotR * DD;        // h_R at [256,512) -> xr[d]
#pragma unroll 4
            for (int d = 0; d < HH; d++) {
                float x = xl[d];
                float4 w = *(const float4*)(Wcomp + (size_t)d * FIVEH + k0);
                acc.x += x * w.x; acc.y += x * w.y; acc.z += x * w.z; acc.w += x * w.w;
            }
#pragma unroll 4
            for (int d = HH; d < DD; d++) {
                float x = xr[d];
                float4 w = *(const float4*)(Wcomp + (size_t)d * FIVEH + k0);
                acc.x += x * w.x; acc.y += x * w.y; acc.z += x * w.z; acc.w += x * w.w;
            }
            *(float4*)(aout + k0) = acc;
        }
        __syncthreads();

        // ---- gates + write comp into slotL; bookkeeping shifts in parallel ----
        if (tid < HH) {
            float iv = aout[tid];
            float fl = aout[HH + tid];
            float fr = aout[2 * HH + tid];
            float ov = aout[3 * HH + tid];
            float gc = aout[4 * HH + tid];
            float lc = st[slotL * DD + tid];
            float rc = st[slotR * DD + tid];
            float c  = sigm(fl) * lc + sigm(fr) * rc + sigm(iv) * tanhf(gc);
            float hh = sigm(ov) * tanhf(c);
            st[slotL * DD + tid]      = c;
            st[slotL * DD + HH + tid] = hh;
        } else if (tid == 256) {
            for (int j = idx + 1; j <= n - 2; j++) ord[j] = ord[j + 1];
        } else if (tid == 257) {
            for (int j = idx + 1; j <= n - 3; j++) logits[j] = logits[j + 1];
        }
        __syncthreads();

        // ---- recompute the two affected logits (new indexing; valid pairs 0..n-3)
        const int u = tid & 127;
        const int pos = tid >> 7;                 // 0,1 compute; 2 idle
        const int p = (pos == 0) ? (idx - 1) : idx;
        const bool valid = (pos == 0) ? (idx >= 1)
                         : (pos == 1) ? (idx <= n - 3) : false;
        float v = 0.0f;
        if (valid) {
            const int sa = ord[p], sb = ord[p + 1];
            const float* ha = st + sa * DD + HH;
            const float* hb = st + sb * DD + HH;
            float a = bsel1[u];
#pragma unroll 8
            for (int d = 0; d < HH; d++) a += ha[d] * Wsel1[(size_t)d * SELD + u];
#pragma unroll 8
            for (int d = 0; d < HH; d++) a += hb[d] * Wsel1[(size_t)(HH + d) * SELD + u];
            v = tanhf(a) * Wsel2[u];
        }
        for (int off = 16; off; off >>= 1) v += __shfl_down_sync(0xFFFFFFFFu, v, off);
        if ((tid & 31) == 0 && tid < 256) selred[tid >> 5] = v;
        __syncthreads();
        if ((tid == 0 || tid == 128) && valid) {
            int w0 = (tid >> 5);  // 0 or 4
            logits[p] = selred[w0] + selred[w0 + 1] + selred[w0 + 2] + selred[w0 + 3] + bsel2[0];
        }
        __syncthreads();
    }

    if (tid < HH) g_hroot[b * HH + tid] = st[ord[0] * DD + HH + tid];
}

// ---------------------------------------------------------------------------
// Kernel 3: final MLP per batch. 256 threads per block.
// ---------------------------------------------------------------------------
__global__ __launch_bounds__(256) void mlp_kernel(
    const float* __restrict__ Wm1, const float* __restrict__ bm1,
    const float* __restrict__ Wm2, const float* __restrict__ bm2,
    const float* __restrict__ Wout, const float* __restrict__ bout,
    float* __restrict__ out)
{
    __shared__ float hroot[HH];
    __shared__ float x1[MLPD];
    __shared__ float x2[MLPD];
    __shared__ float ored[NCD][32];

    const int b = blockIdx.x;
    const int tid = threadIdx.x;

    hroot[tid] = g_hroot[b * HH + tid & 255 ? b * HH + tid : b * HH];  // placeholder avoided below
    __syncthreads();
    // (re-load cleanly; the line above is overwritten to keep logic simple)
    hroot[tid] = g_hroot[b * HH + tid];
    __syncthreads();

    const int c0 = tid * 4;
    {
        float4 acc = *(const float4*)(bm1 + c0);
#pragma unroll 4
        for (int d = 0; d < HH; d++) {
            float x = hroot[d];
            float4 w = *(const float4*)(Wm1 + (size_t)d * MLPD + c0);
            acc.x += x * w.x; acc.y += x * w.y; acc.z += x * w.z; acc.w += x * w.w;
        }
        x1[c0 + 0] = fmaxf(acc.x, 0.0f);
        x1[c0 + 1] = fmaxf(acc.y, 0.0f);
        x1[c0 + 2] = fmaxf(acc.z, 0.0f);
        x1[c0 + 3] = fmaxf(acc.w, 0.0f);
    }
    __syncthreads();
    {
        float4 acc = *(const float4*)(bm2 + c0);
#pragma unroll 4
        for (int d = 0; d < MLPD; d++) {
            float x = x1[d];
            float4 w = *(const float4*)(Wm2 + (size_t)d * MLPD + c0);
            acc.x += x * w.x; acc.y += x * w.y; acc.z += x * w.z; acc.w += x * w.w;
        }
        x2[c0 + 0] = fmaxf(acc.x, 0.0f);
        x2[c0 + 1] = fmaxf(acc.y, 0.0f);
        x2[c0 + 2] = fmaxf(acc.z, 0.0f);
        x2[c0 + 3] = fmaxf(acc.w, 0.0f);
    }
    __syncthreads();
    if (tid < 96) {
        int c = tid % 3, seg = tid / 3;
        float a = 0.0f;
        for (int k = seg; k < MLPD; k += 32) a += x2[k] * Wout[(size_t)k * NCD + c];
        ored[c][seg] = a;
    }
    __syncthreads();
    if (tid < NCD) {
        float a = bout[tid];
        for (int s = 0; s < 32; s++) a += ored[tid][s];
        out[b * NCD + tid] = a;
    }
}

// ---------------------------------------------------------------------------
extern "C" void kernel_launch(void* const* d_in, const int* in_sizes, int n_in,
                              void* d_out, int out_size)
{
    const int*   sent  = (const int*)d_in[0];
    /* d_in[1] = transitions (unused by reference) */
    const float* emb   = (const float*)d_in[2];
    const float* Wenc  = (const float*)d_in[3];
    const float* benc  = (const float*)d_in[4];
    const float* Wcomp = (const float*)d_in[5];
    const float* bcomp = (const float*)d_in[6];
    const float* Wsel1 = (const float*)d_in[7];
    const float* bsel1 = (const float*)d_in[8];
    const float* Wsel2 = (const float*)d_in[9];
    const float* bsel2 = (const float*)d_in[10];
    const float* Wm1   = (const float*)d_in[11];
    const float* bm1   = (const float*)d_in[12];
    const float* Wm2   = (const float*)d_in[13];
    const float* bm2   = (const float*)d_in[14];
    const float* Wout  = (const float*)d_in[15];
    const float* bout  = (const float*)d_in[16];
    float* out = (float*)d_out;

    const int smem_selinit = (512 * 16 + SS * HH) * sizeof(float);           // 128 KB
    const int smem_pyramid = (SS * DD + SS + FIVEH + 8) * sizeof(float)
                           + (SS + 1) * sizeof(int) + 256;                   // ~203 KB

    cudaFuncSetAttribute(sel_init_kernel, cudaFuncAttributeMaxDynamicSharedMemorySize, smem_selinit);
    cudaFuncSetAttribute(pyramid_kernel,  cudaFuncAttributeMaxDynamicSharedMemorySize, smem_pyramid);

    encode_kernel<<<dim3(8, 96), 256>>>(sent, emb, Wenc, benc);
    sel_init_kernel<<<dim3(8, BB), 256, smem_selinit>>>(Wsel1, bsel1, Wsel2);
    pyramid_kernel<<<BB, 320, smem_pyramid>>>(Wcomp, bcomp, Wsel1, bsel1, Wsel2, bsel2);
    mlp_kernel<<<BB, 256>>>(Wm1, bm1, Wm2, bm2, Wout, bout, out);
}

// round 3
// speedup vs baseline: 1.0199x; 1.0037x over previous
#include <cuda_runtime.h>
#include <math.h>
#include <stdint.h>

// Problem dims
#define BB    64
#define SS    96
#define EE    300
#define DD    512
#define HH    256
#define SELD  128
#define MLPD  1024
#define NCD   3
#define FIVEH 1280   // 5*HH

// Scratch (static __device__ — no allocation)
__device__ float g_states[BB * SS * DD];      // (b, s, d)  ~12.6 MB
__device__ float g_partial[BB * 8 * SS];      // selector init partials [b][g][j]
__device__ float g_hroot[BB * HH];

__device__ __forceinline__ float sigm(float x) { return 1.0f / (1.0f + expf(-x)); }

// ---------------------------------------------------------------------------
// Kernel 1: encode. states[token, :] = embed[sent[token]] @ W_enc + b_enc
// GEMM (6144 x 300) @ (300 x 512). Tile 64x64, Kc=20, 256 threads, 4x4 micro.
// ---------------------------------------------------------------------------
__global__ __launch_bounds__(256) void encode_kernel(
    const int* __restrict__ sent, const float* __restrict__ emb,
    const float* __restrict__ Wenc, const float* __restrict__ benc)
{
    __shared__ float As[64 * 20];
    __shared__ float Bs[20 * 64];
    __shared__ int words[64];

    const int cb = blockIdx.x;        // col tile (0..7)
    const int tb = blockIdx.y;        // token tile (0..95)
    const int tid = threadIdx.x;
    const int tokenbase = tb * 64;
    const int colbase = cb * 64;

    if (tid < 64) words[tid] = sent[tokenbase + tid];
    __syncthreads();

    const int tx = tid & 15;          // 0..15 -> 4 cols
    const int ty = tid >> 4;          // 0..15 -> 4 rows

    float acc[4][4];
#pragma unroll
    for (int i = 0; i < 4; i++)
#pragma unroll
        for (int j = 0; j < 4; j++) acc[i][j] = 0.0f;

    for (int kb = 0; kb < EE; kb += 20) {
#pragma unroll
        for (int i = 0; i < 5; i++) {
            int e = tid + 256 * i;            // 0..1279
            int r = e / 20, k = e % 20;
            As[e] = emb[(size_t)words[r] * EE + kb + k];
        }
#pragma unroll
        for (int i = 0; i < 5; i++) {
            int e = tid + 256 * i;
            int k = e >> 6, c = e & 63;
            Bs[e] = Wenc[(size_t)(kb + k) * DD + colbase + c];
        }
        __syncthreads();
#pragma unroll
        for (int k = 0; k < 20; k++) {
            float a0 = As[(4 * ty + 0) * 20 + k];
            float a1 = As[(4 * ty + 1) * 20 + k];
            float a2 = As[(4 * ty + 2) * 20 + k];
            float a3 = As[(4 * ty + 3) * 20 + k];
            float b0 = Bs[k * 64 + 4 * tx + 0];
            float b1 = Bs[k * 64 + 4 * tx + 1];
            float b2 = Bs[k * 64 + 4 * tx + 2];
            float b3 = Bs[k * 64 + 4 * tx + 3];
            acc[0][0] += a0 * b0; acc[0][1] += a0 * b1; acc[0][2] += a0 * b2; acc[0][3] += a0 * b3;
            acc[1][0] += a1 * b0; acc[1][1] += a1 * b1; acc[1][2] += a1 * b2; acc[1][3] += a1 * b3;
            acc[2][0] += a2 * b0; acc[2][1] += a2 * b1; acc[2][2] += a2 * b2; acc[2][3] += a2 * b3;
            acc[3][0] += a3 * b0; acc[3][1] += a3 * b1; acc[3][2] += a3 * b2; acc[3][3] += a3 * b3;
        }
        __syncthreads();
    }

#pragma unroll
    for (int i = 0; i < 4; i++) {
        int row = tokenbase + 4 * ty + i;
        int col = colbase + 4 * tx;
        float4 bia = *(const float4*)(benc + col);
        float4 v;
        v.x = acc[i][0] + bia.x; v.y = acc[i][1] + bia.y;
        v.z = acc[i][2] + bia.z; v.w = acc[i][3] + bia.w;
        *(float4*)(g_states + (size_t)row * DD + col) = v;
    }
}

// ---------------------------------------------------------------------------
// Kernel 1b: initial selector logits (partial sums over unit-groups of 16).
// grid (8 groups, 64 batches), 256 threads. smem: W1 slice 32KB + h-half 96KB.
// partial[b][g][j] = sum_{u in group g} tanh(b1[u] + [h_j;h_{j+1}].W1[:,u]) * W2[u]
// ---------------------------------------------------------------------------
__global__ __launch_bounds__(256) void sel_init_kernel(
    const float* __restrict__ Wsel1, const float* __restrict__ bsel1,
    const float* __restrict__ Wsel2)
{
    extern __shared__ float sh[];
    float* w1s = sh;                  // 512*16
    float* hs  = sh + 512 * 16;      // 96*256

    const int g = blockIdx.x, b = blockIdx.y, tid = threadIdx.x;

    for (int i = tid; i < 512 * 16; i += 256) {
        int d = i >> 4, u = i & 15;
        w1s[i] = Wsel1[(size_t)d * SELD + g * 16 + u];
    }
    for (int i = tid; i < SS * HH; i += 256) {
        int s = i >> 8, dd = i & 255;
        hs[i] = g_states[((size_t)(b * SS + s)) * DD + HH + dd];
    }
    __syncthreads();

    const int u16 = tid & 15;
    const int jg = tid >> 4;          // 0..15
    const float bs = bsel1[g * 16 + u16];
    const float w2 = Wsel2[g * 16 + u16];

    for (int jj = 0; jj < 6; jj++) {
        int j = jg + 16 * jj;
        float v = 0.0f;
        if (j < SS - 1) {
            float a = bs;
            const float* ha = hs + j * HH;
            const float* hb = hs + (j + 1) * HH;
#pragma unroll 8
            for (int d = 0; d < HH; d++) a += ha[d] * w1s[d * 16 + u16];
#pragma unroll 8
            for (int d = 0; d < HH; d++) a += hb[d] * w1s[(HH + d) * 16 + u16];
            v = tanhf(a) * w2;
        }
        for (int off = 8; off; off >>= 1) v += __shfl_down_sync(0xFFFFFFFFu, v, off, 16);
        if (u16 == 0 && j < SS - 1) g_partial[(b * 8 + g) * SS + j] = v;
    }
}

// ---------------------------------------------------------------------------
// Kernel 2: per-batch pyramid scan. One block per batch, 320 threads.
// States in smem (96x512). ord[] indirection, incremental logit updates.
// ---------------------------------------------------------------------------
__global__ __launch_bounds__(320, 1) void pyramid_kernel(
    const float* __restrict__ Wcomp, const float* __restrict__ bcomp,
    const float* __restrict__ Wsel1, const float* __restrict__ bsel1,
    const float* __restrict__ Wsel2, const float* __restrict__ bsel2)
{
    extern __shared__ float sh[];
    float* st     = sh;                       // 96*512
    float* logits = st + SS * DD;             // 96
    float* aout   = logits + SS;              // 1280
    float* selred = aout + FIVEH;             // 8
    int*   ord    = (int*)(selred + 8);       // 96
    int*   sidx   = ord + SS;                 // 1

    const int b = blockIdx.x;
    const int tid = threadIdx.x;

    // load this batch's states
    const float* src = g_states + (size_t)b * SS * DD;
    for (int i = tid; i < SS * DD; i += 320) st[i] = src[i];

    if (tid < SS - 1) {
        float a = bsel2[0];
        for (int g = 0; g < 8; g++) a += g_partial[(b * 8 + g) * SS + tid];
        logits[tid] = a;
    }
    if (tid < SS) ord[tid] = tid;
    __syncthreads();

    for (int t = 0; t < SS - 1; t++) {
        const int n = SS - t;
        const int npairs = n - 1;

        // ---- argmax over valid logits (warp 0, ties -> lowest index) ----
        if (tid < 32) {
            float bv = -1e30f; int bi = 0x7FFFFFFF;
            for (int j = tid; j < npairs; j += 32) {
                float v = logits[j];
                if (v > bv) { bv = v; bi = j; }
            }
            for (int off = 16; off; off >>= 1) {
                float ov = __shfl_down_sync(0xFFFFFFFFu, bv, off);
                int   oi = __shfl_down_sync(0xFFFFFFFFu, bi, off);
                if (ov > bv || (ov == bv && oi < bi)) { bv = ov; bi = oi; }
            }
            if (tid == 0) *sidx = bi;
        }
        __syncthreads();
        const int idx = *sidx;
        const int slotL = ord[idx];
        const int slotR = ord[idx + 1];

        // ---- compose GEMV: a = [h_L; h_R] @ W_comp + b_comp (1280 outputs) ----
        {
            const int k0 = tid * 4;
            float4 acc = *(const float4*)(bcomp + k0);
            const float* xl = st + slotL * DD + HH;   // h_L, d in [0,256)
            const float* xr = st + slotR * DD;        // h_R at [256,512) -> xr[d]
#pragma unroll 4
            for (int d = 0; d < HH; d++) {
                float x = xl[d];
                float4 w = *(const float4*)(Wcomp + (size_t)d * FIVEH + k0);
                acc.x += x * w.x; acc.y += x * w.y; acc.z += x * w.z; acc.w += x * w.w;
            }
#pragma unroll 4
            for (int d = HH; d < DD; d++) {
                float x = xr[d];
                float4 w = *(const float4*)(Wcomp + (size_t)d * FIVEH + k0);
                acc.x += x * w.x; acc.y += x * w.y; acc.z += x * w.z; acc.w += x * w.w;
            }
            *(float4*)(aout + k0) = acc;
        }
        __syncthreads();

        // ---- gates + write comp into slotL; bookkeeping shifts in parallel ----
        if (tid < HH) {
            float iv = aout[tid];
            float fl = aout[HH + tid];
            float fr = aout[2 * HH + tid];
            float ov = aout[3 * HH + tid];
            float gc = aout[4 * HH + tid];
            float lc = st[slotL * DD + tid];
            float rc = st[slotR * DD + tid];
            float c  = sigm(fl) * lc + sigm(fr) * rc + sigm(iv) * tanhf(gc);
            float hh = sigm(ov) * tanhf(c);
            st[slotL * DD + tid]      = c;
            st[slotL * DD + HH + tid] = hh;
        } else if (tid == 256) {
            for (int j = idx + 1; j <= n - 2; j++) ord[j] = ord[j + 1];
        } else if (tid == 257) {
            for (int j = idx + 1; j <= n - 3; j++) logits[j] = logits[j + 1];
        }
        __syncthreads();

        // ---- recompute the two affected logits (new indexing; valid pairs 0..n-3)
        const int u = tid & 127;
        const int pos = tid >> 7;                 // 0,1 compute; 2 idle
        const int p = (pos == 0) ? (idx - 1) : idx;
        const bool valid = (pos == 0) ? (idx >= 1)
                         : (pos == 1) ? (idx <= n - 3) : false;
        float v = 0.0f;
        if (valid) {
            const int sa = ord[p], sb = ord[p + 1];
            const float* ha = st + sa * DD + HH;
            const float* hb = st + sb * DD + HH;
            float a = bsel1[u];
#pragma unroll 8
            for (int d = 0; d < HH; d++) a += ha[d] * Wsel1[(size_t)d * SELD + u];
#pragma unroll 8
            for (int d = 0; d < HH; d++) a += hb[d] * Wsel1[(size_t)(HH + d) * SELD + u];
            v = tanhf(a) * Wsel2[u];
        }
        for (int off = 16; off; off >>= 1) v += __shfl_down_sync(0xFFFFFFFFu, v, off);
        if ((tid & 31) == 0 && tid < 256) selred[tid >> 5] = v;
        __syncthreads();
        if ((tid == 0 || tid == 128) && valid) {
            int w0 = (tid >> 5);  // 0 or 4
            logits[p] = selred[w0] + selred[w0 + 1] + selred[w0 + 2] + selred[w0 + 3] + bsel2[0];
        }
        __syncthreads();
    }

    if (tid < HH) g_hroot[b * HH + tid] = st[ord[0] * DD + HH + tid];
}

// ---------------------------------------------------------------------------
// Kernel 3: final MLP per batch. 256 threads per block.
// ---------------------------------------------------------------------------
__global__ __launch_bounds__(256) void mlp_kernel(
    const float* __restrict__ Wm1, const float* __restrict__ bm1,
    const float* __restrict__ Wm2, const float* __restrict__ bm2,
    const float* __restrict__ Wout, const float* __restrict__ bout,
    float* __restrict__ out)
{
    __shared__ float hroot[HH];
    __shared__ float x1[MLPD];
    __shared__ float x2[MLPD];
    __shared__ float ored[NCD][32];

    const int b = blockIdx.x;
    const int tid = threadIdx.x;

    hroot[tid] = g_hroot[b * HH + tid & 255 ? b * HH + tid : b * HH];  // placeholder avoided below
    __syncthreads();
    // (re-load cleanly; the line above is overwritten to keep logic simple)
    hroot[tid] = g_hroot[b * HH + tid];
    __syncthreads();

    const int c0 = tid * 4;
    {
        float4 acc = *(const float4*)(bm1 + c0);
#pragma unroll 4
        for (int d = 0; d < HH; d++) {
            float x = hroot[d];
            float4 w = *(const float4*)(Wm1 + (size_t)d * MLPD + c0);
            acc.x += x * w.x; acc.y += x * w.y; acc.z += x * w.z; acc.w += x * w.w;
        }
        x1[c0 + 0] = fmaxf(acc.x, 0.0f);
        x1[c0 + 1] = fmaxf(acc.y, 0.0f);
        x1[c0 + 2] = fmaxf(acc.z, 0.0f);
        x1[c0 + 3] = fmaxf(acc.w, 0.0f);
    }
    __syncthreads();
    {
        float4 acc = *(const float4*)(bm2 + c0);
#pragma unroll 4
        for (int d = 0; d < MLPD; d++) {
            float x = x1[d];
            float4 w = *(const float4*)(Wm2 + (size_t)d * MLPD + c0);
            acc.x += x * w.x; acc.y += x * w.y; acc.z += x * w.z; acc.w += x * w.w;
        }
        x2[c0 + 0] = fmaxf(acc.x, 0.0f);
        x2[c0 + 1] = fmaxf(acc.y, 0.0f);
        x2[c0 + 2] = fmaxf(acc.z, 0.0f);
        x2[c0 + 3] = fmaxf(acc.w, 0.0f);
    }
    __syncthreads();
    if (tid < 96) {
        int c = tid % 3, seg = tid / 3;
        float a = 0.0f;
        for (int k = seg; k < MLPD; k += 32) a += x2[k] * Wout[(size_t)k * NCD + c];
        ored[c][seg] = a;
    }
    __syncthreads();
    if (tid < NCD) {
        float a = bout[tid];
        for (int s = 0; s < 32; s++) a += ored[tid][s];
        out[b * NCD + tid] = a;
    }
}

// ---------------------------------------------------------------------------
extern "C" void kernel_launch(void* const* d_in, const int* in_sizes, int n_in,
                              void* d_out, int out_size)
{
    const int*   sent  = (const int*)d_in[0];
    /* d_in[1] = transitions (unused by reference) */
    const float* emb   = (const float*)d_in[2];
    const float* Wenc  = (const float*)d_in[3];
    const float* benc  = (const float*)d_in[4];
    const float* Wcomp = (const float*)d_in[5];
    const float* bcomp = (const float*)d_in[6];
    const float* Wsel1 = (const float*)d_in[7];
    const float* bsel1 = (const float*)d_in[8];
    const float* Wsel2 = (const float*)d_in[9];
    const float* bsel2 = (const float*)d_in[10];
    const float* Wm1   = (const float*)d_in[11];
    const float* bm1   = (const float*)d_in[12];
    const float* Wm2   = (const float*)d_in[13];
    const float* bm2   = (const float*)d_in[14];
    const float* Wout  = (const float*)d_in[15];
    const float* bout  = (const float*)d_in[16];
    float* out = (float*)d_out;

    const int smem_selinit = (512 * 16 + SS * HH) * sizeof(float);           // 128 KB
    const int smem_pyramid = (SS * DD + SS + FIVEH + 8) * sizeof(float)
                           + (SS + 1) * sizeof(int) + 256;                   // ~203 KB

    cudaFuncSetAttribute(sel_init_kernel, cudaFuncAttributeMaxDynamicSharedMemorySize, smem_selinit);
    cudaFuncSetAttribute(pyramid_kernel,  cudaFuncAttributeMaxDynamicSharedMemorySize, smem_pyramid);

    encode_kernel<<<dim3(8, 96), 256>>>(sent, emb, Wenc, benc);
    sel_init_kernel<<<dim3(8, BB), 256, smem_selinit>>>(Wsel1, bsel1, Wsel2);
    pyramid_kernel<<<BB, 320, smem_pyramid>>>(Wcomp, bcomp, Wsel1, bsel1, Wsel2, bsel2);
    mlp_kernel<<<BB, 256>>>(Wm1, bm1, Wm2, bm2, Wout, bout, out);
}

// round 6
// speedup vs baseline: 1.6378x; 1.6059x over previous
#include <cuda_runtime.h>
#include <math.h>
#include <stdint.h>

#define BB    64
#define SS    96
#define EE    300
#define DD    512
#define HH    256
#define MLPD  1024
#define FIVEH 1280
#define ROWS  191      // 96 leaves + 95 merge rows; root = row 190
#define NCTA  128
#define SX    1040     // s_x row stride (floats)

__device__ float g_states[BB * ROWS * DD];    // rows write-once per run
__device__ float g_P[BB * ROWS * 256];        // selector projections [L(128)|R(128)]
__device__ float g_a[BB * FIVEH];
__device__ float g_x1[BB * MLPD];
__device__ float g_x2[BB * MLPD];
__device__ unsigned g_barcnt;
__device__ volatile unsigned g_bargen;

__device__ __forceinline__ float sigm(float x) { return 1.0f / (1.0f + expf(-x)); }

__device__ __forceinline__ void gridbar() {
    __syncthreads();
    if (threadIdx.x == 0) {
        unsigned gen = g_bargen;
        __threadfence();
        if (atomicAdd(&g_barcnt, 1u) == NCTA - 1u) {
            g_barcnt = 0u;
            __threadfence();
            g_bargen = gen + 1u;
        } else {
            while (g_bargen == gen) { }
        }
        __threadfence();
    }
    __syncthreads();
}

// pair logit: full-warp; result valid on lane 0.
__device__ __forceinline__ float pair_logit(int b, int ra, int rb,
    const float* __restrict__ b1, const float* __restrict__ w2, int lane)
{
    int u = lane * 4;
    float4 pl = __ldcg((const float4*)&g_P[((size_t)b * ROWS + ra) * 256 + u]);
    float4 pr = __ldcg((const float4*)&g_P[((size_t)b * ROWS + rb) * 256 + 128 + u]);
    float4 bb = *(const float4*)&b1[u];
    float4 ww = *(const float4*)&w2[u];
    float s = tanhf(pl.x + pr.x + bb.x) * ww.x + tanhf(pl.y + pr.y + bb.y) * ww.y
            + tanhf(pl.z + pr.z + bb.z) * ww.z + tanhf(pl.w + pr.w + bb.w) * ww.w;
    for (int o = 16; o; o >>= 1) s += __shfl_down_sync(0xFFFFFFFFu, s, o);
    return s;
}

// ---------------------------------------------------------------------------
// encode: states[b][s][:] = embed[sent[b,s]] @ W_enc + b_enc   (rows 0..95)
// ---------------------------------------------------------------------------
__global__ __launch_bounds__(256) void encode_kernel(
    const int* __restrict__ sent, const float* __restrict__ emb,
    const float* __restrict__ Wenc, const float* __restrict__ benc)
{
    __shared__ float As[64 * 20];
    __shared__ float Bs[20 * 64];
    __shared__ int words[64];
    const int cb = blockIdx.x, tb = blockIdx.y, tid = threadIdx.x;
    const int tokenbase = tb * 64, colbase = cb * 64;
    if (tid < 64) words[tid] = sent[tokenbase + tid];
    __syncthreads();
    const int tx = tid & 15, ty = tid >> 4;
    float acc[4][4];
#pragma unroll
    for (int i = 0; i < 4; i++)
#pragma unroll
        for (int j = 0; j < 4; j++) acc[i][j] = 0.0f;
    for (int kb = 0; kb < EE; kb += 20) {
#pragma unroll
        for (int i = 0; i < 5; i++) {
            int e = tid + 256 * i, r = e / 20, k = e % 20;
            As[e] = emb[(size_t)words[r] * EE + kb + k];
        }
#pragma unroll
        for (int i = 0; i < 5; i++) {
            int e = tid + 256 * i, k = e >> 6, c = e & 63;
            Bs[e] = Wenc[(size_t)(kb + k) * DD + colbase + c];
        }
        __syncthreads();
#pragma unroll
        for (int k = 0; k < 20; k++) {
            float a0 = As[(4 * ty + 0) * 20 + k], a1 = As[(4 * ty + 1) * 20 + k];
            float a2 = As[(4 * ty + 2) * 20 + k], a3 = As[(4 * ty + 3) * 20 + k];
            float b0 = Bs[k * 64 + 4 * tx + 0], b1 = Bs[k * 64 + 4 * tx + 1];
            float b2 = Bs[k * 64 + 4 * tx + 2], b3 = Bs[k * 64 + 4 * tx + 3];
            acc[0][0] += a0 * b0; acc[0][1] += a0 * b1; acc[0][2] += a0 * b2; acc[0][3] += a0 * b3;
            acc[1][0] += a1 * b0; acc[1][1] += a1 * b1; acc[1][2] += a1 * b2; acc[1][3] += a1 * b3;
            acc[2][0] += a2 * b0; acc[2][1] += a2 * b1; acc[2][2] += a2 * b2; acc[2][3] += a2 * b3;
            acc[3][0] += a3 * b0; acc[3][1] += a3 * b1; acc[3][2] += a3 * b2; acc[3][3] += a3 * b3;
        }
        __syncthreads();
    }
#pragma unroll
    for (int i = 0; i < 4; i++) {
        int tok = tokenbase + 4 * ty + i;
        int b = tok / SS, s = tok - b * SS;
        int col = colbase + 4 * tx;
        float4 bia = *(const float4*)(benc + col);
        float4 v;
        v.x = acc[i][0] + bia.x; v.y = acc[i][1] + bia.y;
        v.z = acc[i][2] + bia.z; v.w = acc[i][3] + bia.w;
        *(float4*)(g_states + ((size_t)b * ROWS + s) * DD + col) = v;
    }
}

// ---------------------------------------------------------------------------
// persistent scan: 128 CTAs x 256 threads.
// cta = ctaB(8 batch groups of 8) * 16 + ctaN(16 slices)
// ---------------------------------------------------------------------------
__global__ __launch_bounds__(256, 1) void scan_kernel(
    const float* __restrict__ Wcomp, const float* __restrict__ bcomp,
    const float* __restrict__ Wsel1, const float* __restrict__ bsel1,
    const float* __restrict__ Wsel2, const float* __restrict__ bsel2,
    const float* __restrict__ Wm1, const float* __restrict__ bm1,
    const float* __restrict__ Wm2, const float* __restrict__ bm2,
    const float* __restrict__ Wout, const float* __restrict__ bout,
    float* __restrict__ out)
{
    extern __shared__ float sm[];
    float* s_x     = sm;                     // 8*SX      (8320)
    float* s_h     = s_x + 8 * SX;           // 8*260     (2080)
    float* s_part  = s_h + 8 * 260;          // 32*80     (2560)
    float* s_logit = s_part + 2560;          // 2*8*96    (1536)  ping-pong
    int*   s_ord   = (int*)(s_logit + 1536); // 2*8*96    (1536)  ping-pong
    int*   s_sL    = s_ord + 1536;           // 8
    int*   s_sR    = s_sL + 8;               // 8

    const int tid = threadIdx.x;
    const int ctaN = blockIdx.x & 15;
    const int b0 = (blockIdx.x >> 4) * 8;
    const int lane = tid & 31;
    const int wm = tid >> 5;                 // warp -> batch offset (0..7)
    const float b2v = bsel2[0];

    // flattened selector-projection output index for this CTA/thread:
    // k in [0,256): k<128 -> L half (lr=0,u=k); k>=128 -> R half (lr=1,u=k-128)
    const int kP  = ctaN * 16 + (tid & 15);
    const int lrP = kP >> 7;
    const int uP  = kP & 127;

    // ---- P-init: projections for leaf rows 0..95 (2 slots per pass) ----
    {
        const int pm = tid >> 5;             // batch
        const int sl = (tid >> 4) & 1;       // slot within pass
        const float* w = Wsel1 + (size_t)(lrP * 256) * 128 + uP;
        for (int s0 = 0; s0 < SS; s0 += 2) {
            for (int i = tid; i < 1024; i += 256) {      // 8 b x 2 slots x 64 f4
                int m = i >> 7, r = i & 127, ssl = r >> 6, dq = r & 63;
                *(float4*)&s_x[m * SX + ssl * 260 + dq * 4] =
                    __ldcg((const float4*)&g_states[((size_t)(b0 + m) * ROWS + s0 + ssl) * DD + HH + dq * 4]);
            }
            __syncthreads();
            const float* xb = s_x + pm * SX + sl * 260;
            float acc = 0.0f;
#pragma unroll 8
            for (int d = 0; d < 256; d++) acc += xb[d] * w[(size_t)d * 128];
            g_P[((size_t)(b0 + pm) * ROWS + s0 + sl) * 256 + kP] = acc;
            __syncthreads();
        }
    }
    gridbar();

    // ---- initial logits + ord into buffer 0 (warp wm owns batch b0+wm) ----
    {
        const int b = b0 + wm, mo = wm * SS;
        for (int j = lane; j < SS; j += 32) s_ord[mo + j] = j;
        for (int p = 0; p < SS - 1; p++) {
            float s = pair_logit(b, p, p + 1, bsel1, Wsel2, lane);
            if (lane == 0) s_logit[mo + p] = s + b2v;
        }
    }
    __syncthreads();

    int idxReg = -1;   // per-warp: previous step's merge position

    // ================= main loop =================
    for (int t = 0; t < SS - 1; t++) {
        const int npairs = SS - 1 - t;
        const int co = (t & 1) * 768 + wm * SS;
        // ---- part 1: per-batch double-buffered shift + recompute + argmax ----
        {
            const int b = b0 + wm;
            if (t > 0) {
                const int po = ((t - 1) & 1) * 768 + wm * SS;
                const int idx = idxReg;
                const int limO = SS - t - 1, limL = SS - t - 2;
                for (int j = lane; j <= limO; j += 32)
                    s_ord[co + j] = (j < idx) ? s_ord[po + j]
                                  : (j == idx ? SS + t - 1 : s_ord[po + j + 1]);
                for (int j = lane; j <= limL; j += 32)
                    s_logit[co + j] = (j < idx - 1) ? s_logit[po + j]
                                    : ((j > idx) ? s_logit[po + j + 1] : -1e30f);
                __syncwarp();
#pragma unroll
                for (int pi = 0; pi < 2; pi++) {
                    int p = idx - 1 + pi;
                    if (p >= 0 && p <= limL) {
                        float s = pair_logit(b, s_ord[co + p], s_ord[co + p + 1], bsel1, Wsel2, lane);
                        if (lane == 0) s_logit[co + p] = s + b2v;
                    }
                    __syncwarp();
                }
            }
            // argmax (ties -> lowest index, matches jnp.argmax)
            float bv = -1e30f; int bi = 1 << 30;
            for (int j = lane; j < npairs; j += 32) {
                float v = s_logit[co + j];
                if (v > bv) { bv = v; bi = j; }
            }
            for (int o = 16; o; o >>= 1) {
                float ov = __shfl_down_sync(0xFFFFFFFFu, bv, o);
                int   oi = __shfl_down_sync(0xFFFFFFFFu, bi, o);
                if (ov > bv || (ov == bv && oi < bi)) { bv = ov; bi = oi; }
            }
            idxReg = __shfl_sync(0xFFFFFFFFu, bi, 0);
            if (lane == 0) {
                s_sL[wm] = s_ord[co + idxReg];
                s_sR[wm] = s_ord[co + idxReg + 1];
            }
        }
        __syncthreads();

        // ---- part 2: compose GEMM (64x1280x512 chip-wide) ----
        for (int i = tid; i < 1024; i += 256) {   // stage x = [hL;hR] per batch
            int m = i >> 7, dq = i & 127;
            int slot = (dq < 64) ? s_sL[m] : s_sR[m];
            *(float4*)&s_x[m * SX + dq * 4] =
                __ldcg((const float4*)&g_states[((size_t)(b0 + m) * ROWS + slot) * DD + HH + (dq & 63) * 4]);
        }
        __syncthreads();
        if (tid < 160) {
            const int q = tid % 20, r = tid / 20;
            const int mh = r & 1, ks = r >> 1;
            const int c0 = q * 4, col0 = ctaN * 80 + c0, mb = mh * 4;
            const float* Wb = Wcomp + (size_t)(ks * 128) * FIVEH + col0;
            const float* x0 = s_x + (mb + 0) * SX + ks * 128;
            const float* x1 = s_x + (mb + 1) * SX + ks * 128;
            const float* x2 = s_x + (mb + 2) * SX + ks * 128;
            const float* x3 = s_x + (mb + 3) * SX + ks * 128;
            float ac[4][4] = {};
#pragma unroll 4
            for (int d = 0; d < 128; d++) {
                float4 w = *(const float4*)(Wb + (size_t)d * FIVEH);
                float v0 = x0[d], v1 = x1[d], v2 = x2[d], v3 = x3[d];
                ac[0][0] += v0 * w.x; ac[0][1] += v0 * w.y; ac[0][2] += v0 * w.z; ac[0][3] += v0 * w.w;
                ac[1][0] += v1 * w.x; ac[1][1] += v1 * w.y; ac[1][2] += v1 * w.z; ac[1][3] += v1 * w.w;
                ac[2][0] += v2 * w.x; ac[2][1] += v2 * w.y; ac[2][2] += v2 * w.z; ac[2][3] += v2 * w.w;
                ac[3][0] += v3 * w.x; ac[3][1] += v3 * w.y; ac[3][2] += v3 * w.z; ac[3][3] += v3 * w.w;
            }
#pragma unroll
            for (int mm = 0; mm < 4; mm++)
                *(float4*)&s_part[(ks * 8 + mb + mm) * 80 + c0] =
                    make_float4(ac[mm][0], ac[mm][1], ac[mm][2], ac[mm][3]);
        }
        __syncthreads();
        for (int i = tid; i < 640; i += 256) {
            int m = i / 80, c = i - m * 80;
            int col = ctaN * 80 + c;
            float v = s_part[m * 80 + c] + s_part[(8 + m) * 80 + c]
                    + s_part[(16 + m) * 80 + c] + s_part[(24 + m) * 80 + c] + bcomp[col];
            g_a[(b0 + m) * FIVEH + col] = v;
        }
        gridbar();

        // ---- phase Y: gates -> new row (ctaN==0 writes) + P projection ----
        const int R = SS + t;
        {
            const int u = tid;   // 256 == HH
#pragma unroll 2
            for (int m = 0; m < 8; m++) {
                const int b = b0 + m;
                const float* ab = g_a + (size_t)b * FIVEH + u;
                float iv = __ldcg(ab), fl = __ldcg(ab + HH), fr = __ldcg(ab + 2 * HH);
                float ov = __ldcg(ab + 3 * HH), gc = __ldcg(ab + 4 * HH);
                size_t rb = (size_t)b * ROWS;
                float lc = __ldcg(&g_states[(rb + s_sL[m]) * DD + u]);
                float rc = __ldcg(&g_states[(rb + s_sR[m]) * DD + u]);
                float c = sigm(fl) * lc + sigm(fr) * rc + sigm(iv) * tanhf(gc);
                float h = sigm(ov) * tanhf(c);
                s_h[m * 260 + u] = h;
                if (ctaN == 0) {
                    g_states[(rb + R) * DD + u] = c;
                    g_states[(rb + R) * DD + HH + u] = h;
                }
            }
        }
        __syncthreads();
        {
            const int pm = tid >> 5, half = (tid >> 4) & 1;
            const float* w = Wsel1 + (size_t)(lrP * 256 + half * 128) * 128 + uP;
            const float* hb = s_h + pm * 260 + half * 128;
            float acc = 0.0f;
#pragma unroll 8
            for (int d = 0; d < 128; d++) acc += hb[d] * w[(size_t)d * 128];
            acc += __shfl_xor_sync(0xFFFFFFFFu, acc, 16);
            if (half == 0)
                g_P[((size_t)(b0 + pm) * ROWS + R) * 256 + kP] = acc;
        }
        gridbar();
    }

    // ================= MLP (root = row 190) =================
    for (int i = tid; i < 2048; i += 256) {   // stage h_root
        int m = i >> 8, d = i & 255;
        s_h[m * 260 + d] = __ldcg(&g_states[((size_t)(b0 + m) * ROWS + 190) * DD + HH + d]);
    }
    __syncthreads();
    {   // layer 1: 64x1024x256
        const int m = tid >> 5, c32 = tid & 31;
        const int col = ctaN * 64 + c32;
        float a0 = 0, a1 = 0;
        const float* hb = s_h + m * 260;
#pragma unroll 4
        for (int d = 0; d < 256; d++) {
            float hv = hb[d];
            a0 += hv * Wm1[(size_t)d * MLPD + col];
            a1 += hv * Wm1[(size_t)d * MLPD + col + 32];
        }
        g_x1[(b0 + m) * MLPD + col]      = fmaxf(a0 + bm1[col], 0.0f);
        g_x1[(b0 + m) * MLPD + col + 32] = fmaxf(a1 + bm1[col + 32], 0.0f);
    }
    gridbar();
    for (int i = tid; i < 2048; i += 256) {   // stage x1
        int m = i >> 8, kq = i & 255;
        *(float4*)&s_x[m * SX + kq * 4] = __ldcg((const float4*)&g_x1[(b0 + m) * MLPD + kq * 4]);
    }
    __syncthreads();
    if (tid < 128) {   // layer 2: 64x1024x1024
        const int m = tid >> 4, q = tid & 15;
        const int col0 = ctaN * 64 + q * 4;
        float4 a = make_float4(0, 0, 0, 0);
        const float* xb = s_x + m * SX;
#pragma unroll 4
        for (int k = 0; k < MLPD; k++) {
            float xv = xb[k];
            float4 w = *(const float4*)&Wm2[(size_t)k * MLPD + col0];
            a.x += xv * w.x; a.y += xv * w.y; a.z += xv * w.z; a.w += xv * w.w;
        }
        float4 bia = *(const float4*)&bm2[col0];
        float4 o;
        o.x = fmaxf(a.x + bia.x, 0.0f); o.y = fmaxf(a.y + bia.y, 0.0f);
        o.z = fmaxf(a.z + bia.z, 0.0f); o.w = fmaxf(a.w + bia.w, 0.0f);
        *(float4*)&g_x2[(b0 + m) * MLPD + col0] = o;
    }
    gridbar();
    if (ctaN == 0) {   // layer 3: 64x3x1024
        for (int i = tid; i < 2048; i += 256) {
            int m = i >> 8, kq = i & 255;
            *(float4*)&s_x[m * SX + kq * 4] = __ldcg((const float4*)&g_x2[(b0 + m) * MLPD + kq * 4]);
        }
        __syncthreads();
        const int b = b0 + wm;
        const float* xb = s_x + wm * SX;
        float a0 = 0, a1 = 0, a2 = 0;
        for (int k = lane; k < MLPD; k += 32) {
            float xv = xb[k];
            a0 += xv * Wout[k * 3 + 0];
            a1 += xv * Wout[k * 3 + 1];
            a2 += xv * Wout[k * 3 + 2];
        }
        for (int o = 16; o; o >>= 1) {
            a0 += __shfl_down_sync(0xFFFFFFFFu, a0, o);
            a1 += __shfl_down_sync(0xFFFFFFFFu, a1, o);
            a2 += __shfl_down_sync(0xFFFFFFFFu, a2, o);
        }
        if (lane == 0) {
            out[b * 3 + 0] = a0 + bout[0];
            out[b * 3 + 1] = a1 + bout[1];
            out[b * 3 + 2] = a2 + bout[2];
        }
    }
}

// ---------------------------------------------------------------------------
extern "C" void kernel_launch(void* const* d_in, const int* in_sizes, int n_in,
                              void* d_out, int out_size)
{
    const int*   sent  = (const int*)d_in[0];
    const float* emb   = (const float*)d_in[2];
    const float* Wenc  = (const float*)d_in[3];
    const float* benc  = (const float*)d_in[4];
    const float* Wcomp = (const float*)d_in[5];
    const float* bcomp = (const float*)d_in[6];
    const float* Wsel1 = (const float*)d_in[7];
    const float* bsel1 = (const float*)d_in[8];
    const float* Wsel2 = (const float*)d_in[9];
    const float* bsel2 = (const float*)d_in[10];
    const float* Wm1   = (const float*)d_in[11];
    const float* bm1   = (const float*)d_in[12];
    const float* Wm2   = (const float*)d_in[13];
    const float* bm2   = (const float*)d_in[14];
    const float* Wout  = (const float*)d_in[15];
    const float* bout  = (const float*)d_in[16];
    float* out = (float*)d_out;

    // floats: 8320 + 2080 + 2560 + 1536 = 14496 ; ints: 1536 + 16
    const int smem_scan = 14496 * 4 + 1552 * 4 + 64;
    cudaFuncSetAttribute(scan_kernel, cudaFuncAttributeMaxDynamicSharedMemorySize, smem_scan);

    encode_kernel<<<dim3(8, 96), 256>>>(sent, emb, Wenc, benc);
    scan_kernel<<<NCTA, 256, smem_scan>>>(Wcomp, bcomp, Wsel1, bsel1, Wsel2, bsel2,
                                          Wm1, bm1, Wm2, bm2, Wout, bout, out);
}

// round 9
// speedup vs baseline: 2.0432x; 1.2476x over previous
#include <cuda_runtime.h>
#include <math.h>
#include <stdint.h>

#define BB    64
#define SS    96
#define EE    300
#define DD    512
#define HH    256
#define MLPD  1024
#define FIVEH 1280
#define ROWS  191     // 96 leaves + 95 merge rows; root = row 190
#define NCTA  128
#define CL    8       // cluster size (CTAs); 16 clusters x 4 batches

__device__ float g_states[BB * ROWS * DD];
__device__ float g_P[BB * ROWS * 256];     // selector projections [L(128)|R(128)]
__device__ float g_a[BB * FIVEH];
__device__ float g_x1[BB * MLPD];
__device__ float g_x2[BB * MLPD];

__device__ __forceinline__ float sigm(float x) { return 1.0f / (1.0f + expf(-x)); }

#define CLUSTER_SYNC() do { \
    asm volatile("barrier.cluster.arrive.aligned;" ::: "memory"); \
    asm volatile("barrier.cluster.wait.aligned;" ::: "memory"); \
} while (0)

// pair logit: full-warp; result valid on lane 0.
__device__ __forceinline__ float pair_logit(int b, int ra, int rb,
    const float* __restrict__ b1, const float* __restrict__ w2, int lane)
{
    int u = lane * 4;
    float4 pl = __ldcg((const float4*)&g_P[((size_t)b * ROWS + ra) * 256 + u]);
    float4 pr = __ldcg((const float4*)&g_P[((size_t)b * ROWS + rb) * 256 + 128 + u]);
    float4 bb = *(const float4*)&b1[u];
    float4 ww = *(const float4*)&w2[u];
    float s = tanhf(pl.x + pr.x + bb.x) * ww.x + tanhf(pl.y + pr.y + bb.y) * ww.y
            + tanhf(pl.z + pr.z + bb.z) * ww.z + tanhf(pl.w + pr.w + bb.w) * ww.w;
    for (int o = 16; o; o >>= 1) s += __shfl_down_sync(0xFFFFFFFFu, s, o);
    return s;
}

// ---------------------------------------------------------------------------
// encode: states[b][s][:] = embed[sent[b,s]] @ W_enc + b_enc   (rows 0..95)
// ---------------------------------------------------------------------------
__global__ __launch_bounds__(256) void encode_kernel(
    const int* __restrict__ sent, const float* __restrict__ emb,
    const float* __restrict__ Wenc, const float* __restrict__ benc)
{
    __shared__ float As[64 * 20];
    __shared__ float Bs[20 * 64];
    __shared__ int words[64];
    const int cb = blockIdx.x, tb = blockIdx.y, tid = threadIdx.x;
    const int tokenbase = tb * 64, colbase = cb * 64;
    if (tid < 64) words[tid] = sent[tokenbase + tid];
    __syncthreads();
    const int tx = tid & 15, ty = tid >> 4;
    float acc[4][4];
#pragma unroll
    for (int i = 0; i < 4; i++)
#pragma unroll
        for (int j = 0; j < 4; j++) acc[i][j] = 0.0f;
    for (int kb = 0; kb < EE; kb += 20) {
#pragma unroll
        for (int i = 0; i < 5; i++) {
            int e = tid + 256 * i, r = e / 20, k = e % 20;
            As[e] = emb[(size_t)words[r] * EE + kb + k];
        }
#pragma unroll
        for (int i = 0; i < 5; i++) {
            int e = tid + 256 * i, k = e >> 6, c = e & 63;
            Bs[e] = Wenc[(size_t)(kb + k) * DD + colbase + c];
        }
        __syncthreads();
#pragma unroll
        for (int k = 0; k < 20; k++) {
            float a0 = As[(4 * ty + 0) * 20 + k], a1 = As[(4 * ty + 1) * 20 + k];
            float a2 = As[(4 * ty + 2) * 20 + k], a3 = As[(4 * ty + 3) * 20 + k];
            float b0 = Bs[k * 64 + 4 * tx + 0], b1 = Bs[k * 64 + 4 * tx + 1];
            float b2 = Bs[k * 64 + 4 * tx + 2], b3 = Bs[k * 64 + 4 * tx + 3];
            acc[0][0] += a0 * b0; acc[0][1] += a0 * b1; acc[0][2] += a0 * b2; acc[0][3] += a0 * b3;
            acc[1][0] += a1 * b0; acc[1][1] += a1 * b1; acc[1][2] += a1 * b2; acc[1][3] += a1 * b3;
            acc[2][0] += a2 * b0; acc[2][1] += a2 * b1; acc[2][2] += a2 * b2; acc[2][3] += a2 * b3;
            acc[3][0] += a3 * b0; acc[3][1] += a3 * b1; acc[3][2] += a3 * b2; acc[3][3] += a3 * b3;
        }
        __syncthreads();
    }
#pragma unroll
    for (int i = 0; i < 4; i++) {
        int tok = tokenbase + 4 * ty + i;
        int b = tok / SS, s = tok - b * SS;
        int col = colbase + 4 * tx;
        float4 bia = *(const float4*)(benc + col);
        float4 v;
        v.x = acc[i][0] + bia.x; v.y = acc[i][1] + bia.y;
        v.z = acc[i][2] + bia.z; v.w = acc[i][3] + bia.w;
        *(float4*)(g_states + ((size_t)b * ROWS + s) * DD + col) = v;
    }
}

// ---------------------------------------------------------------------------
// persistent scan: 128 CTAs as 16 clusters of 8. Cluster c -> batches c*4..+3.
// CTA rank r -> 160-col slice of the 1280 compose outputs, 32-k slice of P.
// ---------------------------------------------------------------------------
__global__ __launch_bounds__(256, 1) __cluster_dims__(CL, 1, 1)
void scan_kernel(
    const float* __restrict__ Wcomp, const float* __restrict__ bcomp,
    const float* __restrict__ Wsel1, const float* __restrict__ bsel1,
    const float* __restrict__ Wsel2, const float* __restrict__ bsel2,
    const float* __restrict__ Wm1, const float* __restrict__ bm1,
    const float* __restrict__ Wm2, const float* __restrict__ bm2,
    const float* __restrict__ Wout, const float* __restrict__ bout,
    float* __restrict__ out)
{
    extern __shared__ float sm[];
    float* s_x     = sm;                     // 4*1040 = 4160
    float* s_h     = s_x + 4160;             // 4*260  = 1040
    float* s_part  = s_h + 1040;             // 5120
    float* s_logit = s_part + 5120;          // 2*4*96 = 768 (ping-pong)
    int*   s_ord   = (int*)(s_logit + 768);  // 2*4*96 = 768 (ping-pong)
    int*   s_sL    = s_ord + 768;            // 4
    int*   s_sR    = s_sL + 4;               // 4

    const int tid  = threadIdx.x;
    const int r    = blockIdx.x & (CL - 1);      // cluster rank
    const int b0   = (blockIdx.x >> 3) * 4;      // first batch of cluster
    const int lane = tid & 31;
    const int wid  = tid >> 5;                   // 8 warps
    const float b2v = bsel2[0];

    // P slice for this CTA: kP = r*32 + lane  (k<128 -> L, else R)
    const int kP  = r * 32 + lane;
    const int lrP = kP >> 7;
    const int uP  = kP & 127;
    const int wmm = wid & 3;                     // batch for warp-tasks
    const int wdh = wid >> 2;                    // d-half for warp-tasks

    // ================= P-init: leaf rows 0..95, 4 rows per pass =================
    {
        const float* wcol = Wsel1 + (size_t)(lrP * 256 + wdh * 128) * 128 + uP;
        for (int s0 = 0; s0 < SS; s0 += 4) {
            for (int i = tid; i < 1024; i += 256) {
                int m = i >> 8, rem = i & 255, rr = rem >> 6, dq = rem & 63;
                *(float4*)&s_x[m * 1040 + rr * 260 + dq * 4] =
                    __ldcg((const float4*)&g_states[((size_t)(b0 + m) * ROWS + s0 + rr) * DD + HH + dq * 4]);
            }
            __syncthreads();
#pragma unroll
            for (int rr = 0; rr < 4; rr++) {
                const float* hb = s_x + wmm * 1040 + rr * 260 + wdh * 128;
                float acc = 0.0f;
#pragma unroll 8
                for (int d = 0; d < 128; d++) acc += hb[d] * wcol[(size_t)d * 128];
                s_part[(wmm * 4 + rr) * 64 + wdh * 32 + lane] = acc;
            }
            __syncthreads();
            for (int i = tid; i < 512; i += 256) {           // full 512 items
                int slot = i >> 5, l2 = i & 31;
                int m = slot >> 2, rr = slot & 3;
                float v = s_part[slot * 64 + l2] + s_part[slot * 64 + 32 + l2];
                g_P[((size_t)(b0 + m) * ROWS + s0 + rr) * 256 + r * 32 + l2] = v;
            }
            __syncthreads();
        }
    }
    CLUSTER_SYNC();

    // ================= initial logits + ord (buffer 0), thread-parallel ========
    for (int i = tid; i < 384; i += 256) s_ord[i] = i % SS;
    for (int i = tid; i < 4 * (SS - 1); i += 256) {
        int m = i / (SS - 1), j = i - m * (SS - 1);
        size_t pb = ((size_t)(b0 + m) * ROWS + j) * 256;
        float s = 0.0f;
#pragma unroll 4
        for (int u4 = 0; u4 < 32; u4++) {
            float4 pl = __ldcg((const float4*)&g_P[pb + u4 * 4]);
            float4 pr = __ldcg((const float4*)&g_P[pb + 256 + 128 + u4 * 4]);
            float4 bb = *(const float4*)&bsel1[u4 * 4];
            float4 ww = *(const float4*)&Wsel2[u4 * 4];
            s += tanhf(pl.x + pr.x + bb.x) * ww.x + tanhf(pl.y + pr.y + bb.y) * ww.y
               + tanhf(pl.z + pr.z + bb.z) * ww.z + tanhf(pl.w + pr.w + bb.w) * ww.w;
        }
        s_logit[m * SS + j] = s + b2v;
    }
    __syncthreads();

    int idxReg = -1;

    // ================= main loop =================
    for (int t = 0; t < SS - 1; t++) {
        const int npairs = SS - 1 - t;
        // ---- part 1: bookkeeping + argmax (warps 0-3, one batch each) ----
        if (wid < 4) {
            const int m = wid, b = b0 + m;
            const int co = (t & 1) * 384 + m * SS;
            if (t > 0) {
                const int po = ((t - 1) & 1) * 384 + m * SS;
                const int idx = idxReg;
                const int limO = SS - t - 1, limL = SS - t - 2;
                for (int j = lane; j <= limO; j += 32)
                    s_ord[co + j] = (j < idx) ? s_ord[po + j]
                                  : (j == idx ? SS + t - 1 : s_ord[po + j + 1]);
                for (int j = lane; j <= limL; j += 32)
                    s_logit[co + j] = (j < idx - 1) ? s_logit[po + j]
                                    : ((j > idx) ? s_logit[po + j + 1] : -1e30f);
                __syncwarp();
#pragma unroll
                for (int pi = 0; pi < 2; pi++) {
                    int p = idx - 1 + pi;
                    if (p >= 0 && p <= limL) {
                        float s = pair_logit(b, s_ord[co + p], s_ord[co + p + 1], bsel1, Wsel2, lane);
                        if (lane == 0) s_logit[co + p] = s + b2v;
                    }
                    __syncwarp();
                }
            }
            float bv = -1e30f; int bi = 1 << 30;
            for (int j = lane; j < npairs; j += 32) {
                float v = s_logit[co + j];
                if (v > bv) { bv = v; bi = j; }
            }
            for (int o = 16; o; o >>= 1) {
                float ov = __shfl_down_sync(0xFFFFFFFFu, bv, o);
                int   oi = __shfl_down_sync(0xFFFFFFFFu, bi, o);
                if (ov > bv || (ov == bv && oi < bi)) { bv = ov; bi = oi; }
            }
            idxReg = __shfl_sync(0xFFFFFFFFu, bi, 0);
            if (lane == 0) {
                s_sL[m] = s_ord[co + idxReg];
                s_sR[m] = s_ord[co + idxReg + 1];
            }
        }
        __syncthreads();

        // ---- stage x = [hL;hR] for 4 batches ----
        for (int i = tid; i < 512; i += 256) {
            int m = i >> 7, dq = i & 127;
            int slot = (dq < 64) ? s_sL[m] : s_sR[m];
            *(float4*)&s_x[m * 1040 + dq * 4] =
                __ldcg((const float4*)&g_states[((size_t)(b0 + m) * ROWS + slot) * DD + HH + (dq & 63) * 4]);
        }
        __syncthreads();

        // ---- compose GEMM slice: 4 batches x 160 cols x 512 K, 256 thr balanced ----
        {
            const int q = lane;              // col within 32-block
            const int ks = wid;              // K-slice of 64
            const int d0 = ks * 64;
            const float* Wb = Wcomp + (size_t)d0 * FIVEH + r * 160 + q;
            float ac[4][5];
#pragma unroll
            for (int m = 0; m < 4; m++)
#pragma unroll
                for (int j = 0; j < 5; j++) ac[m][j] = 0.0f;
#pragma unroll 2
            for (int d = 0; d < 64; d++) {
                const float* wr = Wb + (size_t)d * FIVEH;
                float w0 = wr[0], w1 = wr[32], w2 = wr[64], w3 = wr[96], w4 = wr[128];
                float x0 = s_x[0 * 1040 + d0 + d];
                float x1 = s_x[1 * 1040 + d0 + d];
                float x2 = s_x[2 * 1040 + d0 + d];
                float x3 = s_x[3 * 1040 + d0 + d];
                ac[0][0] += x0 * w0; ac[0][1] += x0 * w1; ac[0][2] += x0 * w2; ac[0][3] += x0 * w3; ac[0][4] += x0 * w4;
                ac[1][0] += x1 * w0; ac[1][1] += x1 * w1; ac[1][2] += x1 * w2; ac[1][3] += x1 * w3; ac[1][4] += x1 * w4;
                ac[2][0] += x2 * w0; ac[2][1] += x2 * w1; ac[2][2] += x2 * w2; ac[2][3] += x2 * w3; ac[2][4] += x2 * w4;
                ac[3][0] += x3 * w0; ac[3][1] += x3 * w1; ac[3][2] += x3 * w2; ac[3][3] += x3 * w3; ac[3][4] += x3 * w4;
            }
#pragma unroll
            for (int m = 0; m < 4; m++)
#pragma unroll
                for (int j = 0; j < 5; j++)
                    s_part[(ks * 4 + m) * 160 + j * 32 + q] = ac[m][j];
        }
        __syncthreads();
        for (int i = tid; i < 640; i += 256) {
            int m = i / 160, c = i - m * 160;
            float v = bcomp[r * 160 + c];
#pragma unroll
            for (int ks = 0; ks < 8; ks++) v += s_part[(ks * 4 + m) * 160 + c];
            g_a[(b0 + m) * FIVEH + r * 160 + c] = v;
        }
        CLUSTER_SYNC();

        // ---- gates: all CTAs compute h (for P); rank 0 writes states row R ----
        const int R = SS + t;
        {
            const int u = tid;
#pragma unroll
            for (int m = 0; m < 4; m++) {
                const int b = b0 + m;
                const float* ab = g_a + (size_t)b * FIVEH + u;
                float iv = __ldcg(ab), fl = __ldcg(ab + HH), fr = __ldcg(ab + 2 * HH);
                float ov = __ldcg(ab + 3 * HH), gc = __ldcg(ab + 4 * HH);
                size_t rb = (size_t)b * ROWS;
                float lc = __ldcg(&g_states[(rb + s_sL[m]) * DD + u]);
                float rc = __ldcg(&g_states[(rb + s_sR[m]) * DD + u]);
                float c = sigm(fl) * lc + sigm(fr) * rc + sigm(iv) * tanhf(gc);
                float h = sigm(ov) * tanhf(c);
                s_h[m * 260 + u] = h;
                if (r == 0) {
                    g_states[(rb + R) * DD + u] = c;
                    g_states[(rb + R) * DD + HH + u] = h;
                }
            }
        }
        __syncthreads();

        // ---- P projection for row R (8 warps: 4 batches x 2 d-halves) ----
        {
            const float* wcol = Wsel1 + (size_t)(lrP * 256 + wdh * 128) * 128 + uP;
            const float* hb = s_h + wmm * 260 + wdh * 128;
            float acc = 0.0f;
#pragma unroll 8
            for (int d = 0; d < 128; d++) acc += hb[d] * wcol[(size_t)d * 128];
            s_part[wmm * 64 + wdh * 32 + lane] = acc;
        }
        __syncthreads();
        if (tid < 128) {
            int m = tid >> 5, l2 = tid & 31;
            float v = s_part[m * 64 + l2] + s_part[m * 64 + 32 + l2];
            g_P[((size_t)(b0 + m) * ROWS + R) * 256 + r * 32 + l2] = v;
        }
        CLUSTER_SYNC();
    }

    // ================= MLP (root = row 190) =================
    for (int i = tid; i < 1024; i += 256) {
        int m = i >> 8, d = i & 255;
        s_h[m * 260 + d] = __ldcg(&g_states[((size_t)(b0 + m) * ROWS + 190) * DD + HH + d]);
    }
    __syncthreads();
    {   // layer 1: per CTA 4 batches x 128 cols (of 1024)
        const int m = tid >> 6, cc = tid & 63;
        const int col = r * 128 + cc;
        float a0 = 0, a1 = 0;
        const float* hb = s_h + m * 260;
#pragma unroll 4
        for (int d = 0; d < 256; d++) {
            float hv = hb[d];
            a0 += hv * Wm1[(size_t)d * MLPD + col];
            a1 += hv * Wm1[(size_t)d * MLPD + col + 64];
        }
        g_x1[(b0 + m) * MLPD + col]      = fmaxf(a0 + bm1[col], 0.0f);
        g_x1[(b0 + m) * MLPD + col + 64] = fmaxf(a1 + bm1[col + 64], 0.0f);
    }
    CLUSTER_SYNC();
    for (int i = tid; i < 1024; i += 256) {
        int m = i >> 8, k4 = i & 255;
        *(float4*)&s_x[m * 1040 + k4 * 4] = __ldcg((const float4*)&g_x1[(b0 + m) * MLPD + k4 * 4]);
    }
    __syncthreads();
    {   // layer 2: per CTA 4 batches x 128 cols, K=1024
        const int m = tid >> 6, cc = tid & 63;
        const int col = r * 128 + cc;
        float a0 = 0, a1 = 0;
        const float* xb = s_x + m * 1040;
#pragma unroll 4
        for (int k = 0; k < MLPD; k++) {
            float xv = xb[k];
            a0 += xv * Wm2[(size_t)k * MLPD + col];
            a1 += xv * Wm2[(size_t)k * MLPD + col + 64];
        }
        g_x2[(b0 + m) * MLPD + col]      = fmaxf(a0 + bm2[col], 0.0f);
        g_x2[(b0 + m) * MLPD + col + 64] = fmaxf(a1 + bm2[col + 64], 0.0f);
    }
    CLUSTER_SYNC();
    if (r == 0) {   // layer 3: 4 batches x 3 outputs
        for (int i = tid; i < 1024; i += 256) {
            int m = i >> 8, k4 = i & 255;
            *(float4*)&s_x[m * 1040 + k4 * 4] = __ldcg((const float4*)&g_x2[(b0 + m) * MLPD + k4 * 4]);
        }
        __syncthreads();
        if (wid < 4) {
            const int b = b0 + wid;
            const float* xb = s_x + wid * 1040;
            float a0 = 0, a1 = 0, a2 = 0;
            for (int k = lane; k < MLPD; k += 32) {
                float xv = xb[k];
                a0 += xv * Wout[k * 3 + 0];
                a1 += xv * Wout[k * 3 + 1];
                a2 += xv * Wout[k * 3 + 2];
            }
            for (int o = 16; o; o >>= 1) {
                a0 += __shfl_down_sync(0xFFFFFFFFu, a0, o);
                a1 += __shfl_down_sync(0xFFFFFFFFu, a1, o);
                a2 += __shfl_down_sync(0xFFFFFFFFu, a2, o);
            }
            if (lane == 0) {
                out[b * 3 + 0] = a0 + bout[0];
                out[b * 3 + 1] = a1 + bout[1];
                out[b * 3 + 2] = a2 + bout[2];
            }
        }
    }
}

// ---------------------------------------------------------------------------
extern "C" void kernel_launch(void* const* d_in, const int* in_sizes, int n_in,
                              void* d_out, int out_size)
{
    const int*   sent  = (const int*)d_in[0];
    const float* emb   = (const float*)d_in[2];
    const float* Wenc  = (const float*)d_in[3];
    const float* benc  = (const float*)d_in[4];
    const float* Wcomp = (const float*)d_in[5];
    const float* bcomp = (const float*)d_in[6];
    const float* Wsel1 = (const float*)d_in[7];
    const float* bsel1 = (const float*)d_in[8];
    const float* Wsel2 = (const float*)d_in[9];
    const float* bsel2 = (const float*)d_in[10];
    const float* Wm1   = (const float*)d_in[11];
    const float* bm1   = (const float*)d_in[12];
    const float* Wm2   = (const float*)d_in[13];
    const float* bm2   = (const float*)d_in[14];
    const float* Wout  = (const float*)d_in[15];
    const float* bout  = (const float*)d_in[16];
    float* out = (float*)d_out;

    // floats: 4160 + 1040 + 5120 + 768 = 11088 ; ints: 768 + 8
    const int smem_scan = 11088 * 4 + 776 * 4;
    cudaFuncSetAttribute(scan_kernel, cudaFuncAttributeMaxDynamicSharedMemorySize, smem_scan);

    encode_kernel<<<dim3(8, 96), 256>>>(sent, emb, Wenc, benc);
    scan_kernel<<<NCTA, 256, smem_scan>>>(Wcomp, bcomp, Wsel1, bsel1, Wsel2, bsel2,
                                          Wm1, bm1, Wm2, bm2, Wout, bout, out);
}